// round 7
// baseline (speedup 1.0000x reference)
// SampleScoreModel: softmax-weighted Gaussian-kernel score, fused persistent kernel.
// Round 6: 512 threads/CTA (32 warps/SM at 2 CTAs) to fix latency-boundness;
// per-thread tiles halved to fit 64 regs. Grid 256 = one wave -> epoch barrier safe.
#include <cuda_runtime.h>
#include <math.h>
#include <float.h>

#define B 32
#define D 64
#define NS 65536
#define TILE 256
#define GRID_MAIN (NS / TILE)   // 256
#define THREADS 512

#define ST_STRIDE 256
#define G_STRIDE 256
#define XS_STRIDE 36

// base column swizzle (bits2..4 ^= bits3..5); bijective per 32-block, keeps 4-float granules
#define SW(n) ((n) ^ ((((n) >> 3) & 7) << 2))

// smem layout (floats)
#define OFF_ST 0                         // 64*256 = 16384
#define OFF_G  16384                     // 32*256 = 8192 (combine buf reuses G..+10752)
#define OFF_XS 24576                     // 64*36  = 2304
#define OFF_Q  26880                     // 256
#define OFF_CB 27136                     // 32
#define OFF_MH 27168                     // 2*32
#define OFF_LH 27232                     // 2*32
#define SMEM_FLOATS 27296
#define SMEM_BYTES (SMEM_FLOATS * 4)     // 109,184 B -> 2 CTAs/SM

#define FMA2(acc, a, b) \
    asm("fma.rn.f32x2 %0, %1, %2, %0;" : "+l"(acc) : "l"(a), "l"(b))
#define DUP2(d, f) \
    asm("mov.b64 %0, {%1, %1};" : "=l"(d) : "r"(__float_as_uint(f)))

__device__ __forceinline__ float lo32(unsigned long long u) {
    return __uint_as_float((unsigned)u);
}
__device__ __forceinline__ float hi32(unsigned long long u) {
    return __uint_as_float((unsigned)(u >> 32));
}

__device__ float g_acc[GRID_MAIN][B][D];
__device__ float g_m[GRID_MAIN][B];
__device__ float g_l[GRID_MAIN][B];
__device__ unsigned int g_ctr;   // monotonic epoch counter (never reset; replay-safe)

__global__ __launch_bounds__(THREADS, 2)
void score_fused_kernel(const float* __restrict__ t,
                        const float* __restrict__ x,
                        const float* __restrict__ samples,
                        float* __restrict__ out) {
    extern __shared__ float sm[];
    float* st   = sm + OFF_ST;
    float* G    = sm + OFF_G;
    float* xs   = sm + OFF_XS;
    float* qn_s = sm + OFF_Q;
    float* cb_s = sm + OFF_CB;
    float* mh_s = sm + OFF_MH;   // [2][32] per-half maxes
    float* lh_s = sm + OFF_LH;   // [2][32] per-half sums

    const int tid = threadIdx.x;

    // ---- setup ----
#pragma unroll
    for (int i = tid; i < B * D; i += THREADS) {
        int b = i >> 6, k = i & 63;
        xs[k * XS_STRIDE + b] = x[i];
    }
    if (tid < B) {
        float sig = 0.01f * expf(t[tid] * 9.210340371976184f);
        cb_s[tid] = 0.5f / (sig * sig);
    }

    // ---- coalesced global load: flat float4 index = tid + 512*j ----
    const int d4 = tid & 15;       // float4 column
    const int nr = tid >> 4;       // 0..31
    const float4* sp = (const float4*)samples;
    const size_t base = (size_t)blockIdx.x * (TILE * (D / 4));
    float4 v[8];
#pragma unroll
    for (int j = 0; j < 8; j++) v[j] = sp[base + tid + 512 * j];

    // ---- transpose-store into st with d-dependent swizzle ----
    const int h4st = (d4 >> 1) << 2;
#pragma unroll
    for (int j = 0; j < 8; j++) {
        int n = nr + 32 * j;
        int pc = SW(n) ^ h4st;
        float* p = &st[(4 * d4) * ST_STRIDE + pc];
        p[0 * ST_STRIDE] = v[j].x;
        p[1 * ST_STRIDE] = v[j].y;
        p[2 * ST_STRIDE] = v[j].z;
        p[3 * ST_STRIDE] = v[j].w;
    }
    __syncthreads();

    // ---- q_n = ||s_n||^2, stored at SW(n) ----
    if (tid < TILE) {
        const int pn = SW(tid);
        float q = 0.0f;
#pragma unroll
        for (int k0 = 0; k0 < D; k0 += 8) {
            const int hk = (k0 >> 3) << 2;
            const float* col = &st[k0 * ST_STRIDE + (pn ^ hk)];
#pragma unroll
            for (int kk = 0; kk < 8; kk++) {
                float val = col[kk * ST_STRIDE];
                q = fmaf(val, val, q);
            }
        }
        qn_s[pn] = q;
    }
    __syncthreads();

    // ---- dot GEMM: 16 warps = 8 b-quads x 2 n-halves; thread = 4b x 4n ----
    const int w    = tid >> 5;
    const int lane = tid & 31;
    const int b0   = 4 * (w & 7);
    const int nh   = w >> 3;
    const int pnA  = SW(128 * nh + 4 * lane);

    float gvv[4][4];
    {
        unsigned long long dot2[4][2];
#pragma unroll
        for (int a = 0; a < 4; a++) { dot2[a][0] = 0ull; dot2[a][1] = 0ull; }

#pragma unroll 1
        for (int k0 = 0; k0 < D; k0 += 8) {
            const int hk = (k0 >> 3) << 2;
            const int pA = pnA ^ hk;
#pragma unroll
            for (int kk = 0; kk < 8; kk++) {
                const int k = k0 + kk;
                const float4 xv = *(const float4*)&xs[k * XS_STRIDE + b0];
                unsigned long long xd0, xd1, xd2, xd3;
                DUP2(xd0, xv.x); DUP2(xd1, xv.y); DUP2(xd2, xv.z); DUP2(xd3, xv.w);
                const ulonglong2 s01 = *(const ulonglong2*)&st[k * ST_STRIDE + pA];
                FMA2(dot2[0][0], xd0, s01.x); FMA2(dot2[0][1], xd0, s01.y);
                FMA2(dot2[1][0], xd1, s01.x); FMA2(dot2[1][1], xd1, s01.y);
                FMA2(dot2[2][0], xd2, s01.x); FMA2(dot2[2][1], xd2, s01.y);
                FMA2(dot2[3][0], xd3, s01.x); FMA2(dot2[3][1], xd3, s01.y);
            }
        }

        const float4 qq = *(const float4*)&qn_s[pnA];
#pragma unroll
        for (int a = 0; a < 4; a++) {
            const float c = cb_s[b0 + a];
            gvv[a][0] = c * (2.0f * lo32(dot2[a][0]) - qq.x);
            gvv[a][1] = c * (2.0f * hi32(dot2[a][0]) - qq.y);
            gvv[a][2] = c * (2.0f * lo32(dot2[a][1]) - qq.z);
            gvv[a][3] = c * (2.0f * hi32(dot2[a][1]) - qq.w);
            float m = fmaxf(fmaxf(gvv[a][0], gvv[a][1]), fmaxf(gvv[a][2], gvv[a][3]));
#pragma unroll
            for (int s = 16; s; s >>= 1) m = fmaxf(m, __shfl_xor_sync(0xffffffffu, m, s));
            if (lane == 0) mh_s[nh * 32 + b0 + a] = m;
        }
    }
    __syncthreads();   // both halves' maxes visible

    // ---- exp with full max; weights to G; per-half sums ----
#pragma unroll
    for (int a = 0; a < 4; a++) {
        const float mf = fmaxf(mh_s[b0 + a], mh_s[32 + b0 + a]);
        float p0 = __expf(gvv[a][0] - mf);
        float p1 = __expf(gvv[a][1] - mf);
        float p2 = __expf(gvv[a][2] - mf);
        float p3 = __expf(gvv[a][3] - mf);
        *(float4*)&G[(b0 + a) * G_STRIDE + pnA] = make_float4(p0, p1, p2, p3);
        float l = (p0 + p1) + (p2 + p3);
#pragma unroll
        for (int s = 16; s; s >>= 1) l += __shfl_xor_sync(0xffffffffu, l, s);
        if (lane == 0) lh_s[nh * 32 + b0 + a] = l;
    }
    __syncthreads();

    // ---- acc GEMM: thread = 2b x 8d, 4-way n-split of 64 ----
    const int cell = tid & 127;
    const int qg   = tid >> 7;       // n-split
    const int dg   = cell & 7;
    const int bgg  = cell >> 3;      // 0..15
    const int b0a  = 2 * bgg;
    const int d0   = 8 * dg;
    const int hd   = dg << 2;

    unsigned long long acc2[2][8];
#pragma unroll
    for (int a = 0; a < 2; a++)
#pragma unroll
        for (int r = 0; r < 8; r++) acc2[a][r] = 0ull;

    {
        const int nbase = 64 * qg;
#pragma unroll 2
        for (int n4 = 0; n4 < 64; n4 += 4) {
            const int pg = SW(nbase + n4);
            const int ps = pg ^ hd;
            const ulonglong2 p0 = *(const ulonglong2*)&G[(b0a    ) * G_STRIDE + pg];
            const ulonglong2 p1 = *(const ulonglong2*)&G[(b0a + 1) * G_STRIDE + pg];
#pragma unroll
            for (int r = 0; r < 8; r++) {
                const ulonglong2 sv = *(const ulonglong2*)&st[(d0 + r) * ST_STRIDE + ps];
                FMA2(acc2[0][r], p0.x, sv.x); FMA2(acc2[0][r], p0.y, sv.y);
                FMA2(acc2[1][r], p1.x, sv.x); FMA2(acc2[1][r], p1.y, sv.y);
            }
        }
    }

    float acc[2][8];
#pragma unroll
    for (int a = 0; a < 2; a++)
#pragma unroll
        for (int r = 0; r < 8; r++)
            acc[a][r] = lo32(acc2[a][r]) + hi32(acc2[a][r]);

    __syncthreads();            // done reading G/st; reuse as combine buffer

    // ---- combine 4 n-splits (stride-17 rows: bank-clean) ----
    float* buf = G;             // extends over xs/q dead space: 10752 floats >= 512*17
    {
        float* bp = &buf[tid * 17];
#pragma unroll
        for (int a = 0; a < 2; a++)
#pragma unroll
            for (int r = 0; r < 8; r++) bp[a * 8 + r] = acc[a][r];
    }
    __syncthreads();
    {
        const int cr = tid & 127;
        const int g  = tid >> 7;        // 0..3
        const int a  = g >> 1;
        const int r0 = 4 * (g & 1);
        float4 s4 = make_float4(0.f, 0.f, 0.f, 0.f);
#pragma unroll
        for (int q2 = 0; q2 < 4; q2++) {
            const float* bp = &buf[(q2 * 128 + cr) * 17 + a * 8 + r0];
            s4.x += bp[0]; s4.y += bp[1]; s4.z += bp[2]; s4.w += bp[3];
        }
        const int bglob = 2 * (cr >> 3) + a;
        const int dbase = 8 * (cr & 7) + r0;
        *(float4*)&g_acc[blockIdx.x][bglob][dbase] = s4;
    }
    if (tid < B) {
        g_m[blockIdx.x][tid] = fmaxf(mh_s[tid], mh_s[32 + tid]);
        g_l[blockIdx.x][tid] = lh_s[tid] + lh_s[32 + tid];
    }

    // ---- grid-wide epoch barrier (grid 256 <= 2*148 capacity: one wave, safe) ----
    {
        __shared__ unsigned s_target;
        if (tid == 0) {
            __threadfence();
            unsigned ticket = atomicAdd(&g_ctr, 1u);
            s_target = (ticket / GRID_MAIN + 1u) * GRID_MAIN;
        }
        __syncthreads();
        if (tid == 0) {
            const unsigned tgt = s_target;
            unsigned vseen;
            do {
                asm volatile("ld.acquire.gpu.global.u32 %0, [%1];"
                             : "=r"(vseen) : "l"(&g_ctr));
                if (vseen < tgt) __nanosleep(128);
            } while (vseen < tgt);
        }
        __syncthreads();
    }

    // ---- distributed reduction: CTA owns (b = blk&31, d-octet = blk>>5) ----
    {
        const int b   = blockIdx.x & 31;
        const int d0r = (blockIdx.x >> 5) * 8;
        float* red = sm;

        float mi = 0.0f;
        if (tid < GRID_MAIN) { mi = g_m[tid][b]; red[tid] = mi; }
        __syncthreads();
        if (tid < 32) {
            float m = red[tid];
#pragma unroll
            for (int k = 1; k < 8; k++) m = fmaxf(m, red[tid + 32 * k]);
#pragma unroll
            for (int s = 16; s; s >>= 1) m = fmaxf(m, __shfl_xor_sync(0xffffffffu, m, s));
            if (tid == 0) red[300] = m;
        }
        __syncthreads();
        const float M = red[300];

        float vals[9];
#pragma unroll
        for (int j = 0; j < 9; j++) vals[j] = 0.0f;
        if (tid < GRID_MAIN) {
            const float ei = __expf(mi - M);
            vals[0] = ei * g_l[tid][b];
            const float4 aA = *(const float4*)&g_acc[tid][b][d0r];
            const float4 aB = *(const float4*)&g_acc[tid][b][d0r + 4];
            vals[1] = ei * aA.x; vals[2] = ei * aA.y; vals[3] = ei * aA.z; vals[4] = ei * aA.w;
            vals[5] = ei * aB.x; vals[6] = ei * aB.y; vals[7] = ei * aB.z; vals[8] = ei * aB.w;
        }
#pragma unroll
        for (int s = 16; s; s >>= 1)
#pragma unroll
            for (int j = 0; j < 9; j++)
                vals[j] += __shfl_xor_sync(0xffffffffu, vals[j], s);
        if (tid < GRID_MAIN && (tid & 31) == 0) {
            const int w2 = tid >> 5;
#pragma unroll
            for (int j = 0; j < 9; j++) red[320 + w2 * 12 + j] = vals[j];
        }
        __syncthreads();
        if (tid < 8) {
            float L = 0.0f, A = 0.0f;
#pragma unroll
            for (int w3 = 0; w3 < 8; w3++) {
                L += red[320 + w3 * 12 + 0];
                A += red[320 + w3 * 12 + 1 + tid];
            }
            const float sig = 0.01f * expf(t[b] * 9.210340371976184f);
            out[b * D + d0r + tid] = (1.0f / sig) * (A / L - x[b * D + d0r + tid]);
        }
    }
}

extern "C" void kernel_launch(void* const* d_in, const int* in_sizes, int n_in,
                              void* d_out, int out_size) {
    const float* t = nullptr;
    const float* x = nullptr;
    const float* s = nullptr;
    for (int i = 0; i < n_in; i++) {
        if      (in_sizes[i] == B)      t = (const float*)d_in[i];
        else if (in_sizes[i] == B * D)  x = (const float*)d_in[i];
        else if (in_sizes[i] == NS * D) s = (const float*)d_in[i];
    }
    cudaFuncSetAttribute(score_fused_kernel,
                         cudaFuncAttributeMaxDynamicSharedMemorySize, SMEM_BYTES);
    score_fused_kernel<<<GRID_MAIN, THREADS, SMEM_BYTES>>>(t, x, s, (float*)d_out);
}

// round 11
// speedup vs baseline: 1.0029x; 1.0029x over previous
// SampleScoreModel: softmax-weighted Gaussian-kernel score (flash-attention style).
// Round 11 = round 9/10 resubmitted (two broker-level container failures; the
// kernel itself never compiled or ran — round-3 precedent: identical failure
// mode cleared on resubmit).
//  K1 = round-6 partial phase (512 thr, 2 CTA/SM, f32x2 GEMMs, fused softmax).
//  K2 = distributed reduce: 256 CTAs, one (b, d-octet) slice each; m/l transposed
//       for coalesced reads. Replaces the 7.7us latency-bound grid-32 reduce.
#include <cuda_runtime.h>
#include <math.h>
#include <float.h>

#define B 32
#define D 64
#define NS 65536
#define TILE 256
#define GRID_MAIN (NS / TILE)   // 256
#define THREADS 512

#define ST_STRIDE 256
#define G_STRIDE 256
#define XS_STRIDE 36

#define SW(n) ((n) ^ ((((n) >> 3) & 7) << 2))

// smem layout (floats)
#define OFF_ST 0                         // 64*256 = 16384
#define OFF_G  16384                     // 32*256 = 8192 (combine buf reuses G..+10752)
#define OFF_XS 24576                     // 64*36  = 2304
#define OFF_Q  26880                     // 256
#define OFF_CB 27136                     // 32
#define OFF_MH 27168                     // 2*32
#define OFF_LH 27232                     // 2*32
#define SMEM_FLOATS 27296
#define SMEM_BYTES (SMEM_FLOATS * 4)     // 109,184 B -> 2 CTAs/SM

#define FMA2(acc, a, b) \
    asm("fma.rn.f32x2 %0, %1, %2, %0;" : "+l"(acc) : "l"(a), "l"(b))
#define DUP2(d, f) \
    asm("mov.b64 %0, {%1, %1};" : "=l"(d) : "r"(__float_as_uint(f)))

__device__ __forceinline__ float lo32(unsigned long long u) {
    return __uint_as_float((unsigned)u);
}
__device__ __forceinline__ float hi32(unsigned long long u) {
    return __uint_as_float((unsigned)(u >> 32));
}

__device__ float g_acc[GRID_MAIN][B][D];
__device__ float g_mT[B][GRID_MAIN];    // transposed: coalesced reduce reads
__device__ float g_lT[B][GRID_MAIN];

__global__ __launch_bounds__(THREADS, 2)
void score_partial_kernel(const float* __restrict__ t,
                          const float* __restrict__ x,
                          const float* __restrict__ samples) {
    extern __shared__ float sm[];
    float* st   = sm + OFF_ST;
    float* G    = sm + OFF_G;
    float* xs   = sm + OFF_XS;
    float* qn_s = sm + OFF_Q;
    float* cb_s = sm + OFF_CB;
    float* mh_s = sm + OFF_MH;   // [2][32] per-half maxes
    float* lh_s = sm + OFF_LH;   // [2][32] per-half sums

    const int tid = threadIdx.x;

    // ---- setup ----
#pragma unroll
    for (int i = tid; i < B * D; i += THREADS) {
        int b = i >> 6, k = i & 63;
        xs[k * XS_STRIDE + b] = x[i];
    }
    if (tid < B) {
        float sig = 0.01f * expf(t[tid] * 9.210340371976184f);
        cb_s[tid] = 0.5f / (sig * sig);
    }

    // ---- coalesced global load: flat float4 index = tid + 512*j ----
    const int d4 = tid & 15;
    const int nr = tid >> 4;
    const float4* sp = (const float4*)samples;
    const size_t base = (size_t)blockIdx.x * (TILE * (D / 4));
    float4 v[8];
#pragma unroll
    for (int j = 0; j < 8; j++) v[j] = sp[base + tid + 512 * j];

    // ---- transpose-store into st with d-dependent swizzle ----
    const int h4st = (d4 >> 1) << 2;
#pragma unroll
    for (int j = 0; j < 8; j++) {
        int n = nr + 32 * j;
        int pc = SW(n) ^ h4st;
        float* p = &st[(4 * d4) * ST_STRIDE + pc];
        p[0 * ST_STRIDE] = v[j].x;
        p[1 * ST_STRIDE] = v[j].y;
        p[2 * ST_STRIDE] = v[j].z;
        p[3 * ST_STRIDE] = v[j].w;
    }
    __syncthreads();

    // ---- q_n = ||s_n||^2, stored at SW(n) ----
    if (tid < TILE) {
        const int pn = SW(tid);
        float q = 0.0f;
#pragma unroll
        for (int k0 = 0; k0 < D; k0 += 8) {
            const int hk = (k0 >> 3) << 2;
            const float* col = &st[k0 * ST_STRIDE + (pn ^ hk)];
#pragma unroll
            for (int kk = 0; kk < 8; kk++) {
                float val = col[kk * ST_STRIDE];
                q = fmaf(val, val, q);
            }
        }
        qn_s[pn] = q;
    }
    __syncthreads();

    // ---- dot GEMM: 16 warps = 8 b-quads x 2 n-halves; thread = 4b x 4n ----
    const int w    = tid >> 5;
    const int lane = tid & 31;
    const int b0   = 4 * (w & 7);
    const int nh   = w >> 3;
    const int pnA  = SW(128 * nh + 4 * lane);

    float gvv[4][4];
    {
        unsigned long long dot2[4][2];
#pragma unroll
        for (int a = 0; a < 4; a++) { dot2[a][0] = 0ull; dot2[a][1] = 0ull; }

#pragma unroll 1
        for (int k0 = 0; k0 < D; k0 += 8) {
            const int hk = (k0 >> 3) << 2;
            const int pA = pnA ^ hk;
#pragma unroll
            for (int kk = 0; kk < 8; kk++) {
                const int k = k0 + kk;
                const float4 xv = *(const float4*)&xs[k * XS_STRIDE + b0];
                unsigned long long xd0, xd1, xd2, xd3;
                DUP2(xd0, xv.x); DUP2(xd1, xv.y); DUP2(xd2, xv.z); DUP2(xd3, xv.w);
                const ulonglong2 s01 = *(const ulonglong2*)&st[k * ST_STRIDE + pA];
                FMA2(dot2[0][0], xd0, s01.x); FMA2(dot2[0][1], xd0, s01.y);
                FMA2(dot2[1][0], xd1, s01.x); FMA2(dot2[1][1], xd1, s01.y);
                FMA2(dot2[2][0], xd2, s01.x); FMA2(dot2[2][1], xd2, s01.y);
                FMA2(dot2[3][0], xd3, s01.x); FMA2(dot2[3][1], xd3, s01.y);
            }
        }

        const float4 qq = *(const float4*)&qn_s[pnA];
#pragma unroll
        for (int a = 0; a < 4; a++) {
            const float c = cb_s[b0 + a];
            gvv[a][0] = c * (2.0f * lo32(dot2[a][0]) - qq.x);
            gvv[a][1] = c * (2.0f * hi32(dot2[a][0]) - qq.y);
            gvv[a][2] = c * (2.0f * lo32(dot2[a][1]) - qq.z);
            gvv[a][3] = c * (2.0f * hi32(dot2[a][1]) - qq.w);
            float m = fmaxf(fmaxf(gvv[a][0], gvv[a][1]), fmaxf(gvv[a][2], gvv[a][3]));
#pragma unroll
            for (int s = 16; s; s >>= 1) m = fmaxf(m, __shfl_xor_sync(0xffffffffu, m, s));
            if (lane == 0) mh_s[nh * 32 + b0 + a] = m;
        }
    }
    __syncthreads();

    // ---- exp with full max; weights to G; per-half sums ----
#pragma unroll
    for (int a = 0; a < 4; a++) {
        const float mf = fmaxf(mh_s[b0 + a], mh_s[32 + b0 + a]);
        float p0 = __expf(gvv[a][0] - mf);
        float p1 = __expf(gvv[a][1] - mf);
        float p2 = __expf(gvv[a][2] - mf);
        float p3 = __expf(gvv[a][3] - mf);
        *(float4*)&G[(b0 + a) * G_STRIDE + pnA] = make_float4(p0, p1, p2, p3);
        float l = (p0 + p1) + (p2 + p3);
#pragma unroll
        for (int s = 16; s; s >>= 1) l += __shfl_xor_sync(0xffffffffu, l, s);
        if (lane == 0) lh_s[nh * 32 + b0 + a] = l;
    }
    __syncthreads();

    // ---- acc GEMM: thread = 2b x 8d, 4-way n-split of 64 ----
    const int cell = tid & 127;
    const int qg   = tid >> 7;
    const int dg   = cell & 7;
    const int bgg  = cell >> 3;
    const int b0a  = 2 * bgg;
    const int d0   = 8 * dg;
    const int hd   = dg << 2;

    unsigned long long acc2[2][8];
#pragma unroll
    for (int a = 0; a < 2; a++)
#pragma unroll
        for (int r = 0; r < 8; r++) acc2[a][r] = 0ull;

    {
        const int nbase = 64 * qg;
#pragma unroll 2
        for (int n4 = 0; n4 < 64; n4 += 4) {
            const int pg = SW(nbase + n4);
            const int ps = pg ^ hd;
            const ulonglong2 p0 = *(const ulonglong2*)&G[(b0a    ) * G_STRIDE + pg];
            const ulonglong2 p1 = *(const ulonglong2*)&G[(b0a + 1) * G_STRIDE + pg];
#pragma unroll
            for (int r = 0; r < 8; r++) {
                const ulonglong2 sv = *(const ulonglong2*)&st[(d0 + r) * ST_STRIDE + ps];
                FMA2(acc2[0][r], p0.x, sv.x); FMA2(acc2[0][r], p0.y, sv.y);
                FMA2(acc2[1][r], p1.x, sv.x); FMA2(acc2[1][r], p1.y, sv.y);
            }
        }
    }

    float acc[2][8];
#pragma unroll
    for (int a = 0; a < 2; a++)
#pragma unroll
        for (int r = 0; r < 8; r++)
            acc[a][r] = lo32(acc2[a][r]) + hi32(acc2[a][r]);

    __syncthreads();            // done reading G/st; reuse as combine buffer

    // ---- combine 4 n-splits (stride-17 rows: bank-clean) ----
    float* buf = G;
    {
        float* bp = &buf[tid * 17];
#pragma unroll
        for (int a = 0; a < 2; a++)
#pragma unroll
            for (int r = 0; r < 8; r++) bp[a * 8 + r] = acc[a][r];
    }
    __syncthreads();
    {
        const int cr = tid & 127;
        const int g  = tid >> 7;
        const int a  = g >> 1;
        const int r0 = 4 * (g & 1);
        float4 s4 = make_float4(0.f, 0.f, 0.f, 0.f);
#pragma unroll
        for (int q2 = 0; q2 < 4; q2++) {
            const float* bp = &buf[(q2 * 128 + cr) * 17 + a * 8 + r0];
            s4.x += bp[0]; s4.y += bp[1]; s4.z += bp[2]; s4.w += bp[3];
        }
        const int bglob = 2 * (cr >> 3) + a;
        const int dbase = 8 * (cr & 7) + r0;
        *(float4*)&g_acc[blockIdx.x][bglob][dbase] = s4;
    }
    if (tid < B) {
        g_mT[tid][blockIdx.x] = fmaxf(mh_s[tid], mh_s[32 + tid]);
        g_lT[tid][blockIdx.x] = lh_s[tid] + lh_s[32 + tid];
    }
}

// Distributed reduce: CTA owns (b = blk&31, d-octet = blk>>5). 256 threads,
// thread i handles partial i; coalesced m/l reads; 9-value butterfly reduce.
__global__ __launch_bounds__(256)
void score_reduce_kernel(const float* __restrict__ t,
                         const float* __restrict__ x,
                         float* __restrict__ out) {
    const int b   = blockIdx.x & 31;
    const int d0r = (blockIdx.x >> 5) * 8;
    const int tid = threadIdx.x;
    __shared__ float red[416];

    const float mi = g_mT[b][tid];
    red[tid] = mi;
    __syncthreads();
    if (tid < 32) {
        float m = red[tid];
#pragma unroll
        for (int k = 1; k < 8; k++) m = fmaxf(m, red[tid + 32 * k]);
#pragma unroll
        for (int s = 16; s; s >>= 1) m = fmaxf(m, __shfl_xor_sync(0xffffffffu, m, s));
        if (tid == 0) red[300] = m;
    }
    __syncthreads();
    const float M = red[300];

    const float ei = __expf(mi - M);
    float vals[9];
    vals[0] = ei * g_lT[b][tid];
    {
        const float4 aA = *(const float4*)&g_acc[tid][b][d0r];
        const float4 aB = *(const float4*)&g_acc[tid][b][d0r + 4];
        vals[1] = ei * aA.x; vals[2] = ei * aA.y; vals[3] = ei * aA.z; vals[4] = ei * aA.w;
        vals[5] = ei * aB.x; vals[6] = ei * aB.y; vals[7] = ei * aB.z; vals[8] = ei * aB.w;
    }
#pragma unroll
    for (int s = 16; s; s >>= 1)
#pragma unroll
        for (int j = 0; j < 9; j++)
            vals[j] += __shfl_xor_sync(0xffffffffu, vals[j], s);
    const int w2 = tid >> 5;
    if ((tid & 31) == 0) {
#pragma unroll
        for (int j = 0; j < 9; j++) red[320 + w2 * 12 + j] = vals[j];
    }
    __syncthreads();
    if (tid < 8) {
        float L = 0.0f, A = 0.0f;
#pragma unroll
        for (int w3 = 0; w3 < 8; w3++) {
            L += red[320 + w3 * 12 + 0];
            A += red[320 + w3 * 12 + 1 + tid];
        }
        const float sig = 0.01f * expf(t[b] * 9.210340371976184f);
        out[b * D + d0r + tid] = (1.0f / sig) * (A / L - x[b * D + d0r + tid]);
    }
}

extern "C" void kernel_launch(void* const* d_in, const int* in_sizes, int n_in,
                              void* d_out, int out_size) {
    const float* t = nullptr;
    const float* x = nullptr;
    const float* s = nullptr;
    for (int i = 0; i < n_in; i++) {
        if      (in_sizes[i] == B)      t = (const float*)d_in[i];
        else if (in_sizes[i] == B * D)  x = (const float*)d_in[i];
        else if (in_sizes[i] == NS * D) s = (const float*)d_in[i];
    }
    cudaFuncSetAttribute(score_partial_kernel,
                         cudaFuncAttributeMaxDynamicSharedMemorySize, SMEM_BYTES);
    score_partial_kernel<<<GRID_MAIN, THREADS, SMEM_BYTES>>>(t, x, s);
    score_reduce_kernel<<<GRID_MAIN, 256>>>(t, x, (float*)d_out);
}

// round 12
// speedup vs baseline: 1.0039x; 1.0010x over previous
// SampleScoreModel: softmax-weighted Gaussian-kernel score (flash-attention style).
// Round 12: K1 = r4 fat-tile 256-thread shape, with pre-duplicated xs2 (kills
// DUP2 in the dot loop; xs2 aliases G's region, dead during dot) and direct
// mT/lT writes. K2 = r11 distributed reduce (at its short-kernel floor).
#include <cuda_runtime.h>
#include <math.h>
#include <float.h>

#define B 32
#define D 64
#define NS 65536
#define TILE 256
#define GRID_MAIN (NS / TILE)   // 256
#define THREADS 256

#define ST_STRIDE 256
#define G_STRIDE 256
#define XS2_STRIDE 72           // duplicated x row: 64 values stored twice + pad

#define SW(n) ((n) ^ ((((n) >> 3) & 7) << 2))

// smem layout (floats)
#define OFF_ST 0                         // 64*256 = 16384
#define OFF_G  16384                     // 8192: weights / xs2 alias / combine buf
#define OFF_Q  24576                     // 256
#define OFF_CB 24832                     // 32
#define SMEM_FLOATS 24864
#define SMEM_BYTES (SMEM_FLOATS * 4)     // 99,456 B -> 2 CTAs/SM

#define FMA2(acc, a, b) \
    asm("fma.rn.f32x2 %0, %1, %2, %0;" : "+l"(acc) : "l"(a), "l"(b))

__device__ __forceinline__ float lo32(unsigned long long u) {
    return __uint_as_float((unsigned)u);
}
__device__ __forceinline__ float hi32(unsigned long long u) {
    return __uint_as_float((unsigned)(u >> 32));
}

__device__ float g_acc[GRID_MAIN][B][D];
__device__ float g_mT[B][GRID_MAIN];
__device__ float g_lT[B][GRID_MAIN];

__global__ __launch_bounds__(THREADS, 2)
void score_partial_kernel(const float* __restrict__ t,
                          const float* __restrict__ x,
                          const float* __restrict__ samples) {
    extern __shared__ float sm[];
    float* st   = sm + OFF_ST;
    float* G    = sm + OFF_G;    // weights after dot; xs2 alias during dot
    float* xs2  = sm + OFF_G;    // [k][2b] duplicated x
    float* qn_s = sm + OFF_Q;    // ||s_n||^2 at [SW(n)]
    float* cb_s = sm + OFF_CB;

    const int tid = threadIdx.x;

    // ---- setup: duplicated x transpose + per-b constants ----
#pragma unroll
    for (int i = tid; i < B * D; i += THREADS) {
        int b = i >> 6, k = i & 63;
        float val = x[i];
        xs2[k * XS2_STRIDE + 2 * b]     = val;
        xs2[k * XS2_STRIDE + 2 * b + 1] = val;
    }
    if (tid < B) {
        float sig = 0.01f * expf(t[tid] * 9.210340371976184f);
        cb_s[tid] = 0.5f / (sig * sig);
    }

    // ---- coalesced global load: flat float4 index = tid + 256*j ----
    const int nn2 = tid >> 4;     // row within 16-group
    const int d4  = tid & 15;     // float4 column
    const float4* sp = (const float4*)samples;
    const size_t base = (size_t)blockIdx.x * (TILE * (D / 4));
    float4 v[16];
#pragma unroll
    for (int j = 0; j < 16; j++) v[j] = sp[base + tid + 256 * j];

    // ---- transpose-store into st with d-dependent swizzle ----
    const int h4st = (d4 >> 1) << 2;
#pragma unroll
    for (int j = 0; j < 16; j++) {
        int n = 16 * j + nn2;
        int pc = SW(n) ^ h4st;
        float* p = &st[(4 * d4) * ST_STRIDE + pc];
        p[0 * ST_STRIDE] = v[j].x;
        p[1 * ST_STRIDE] = v[j].y;
        p[2 * ST_STRIDE] = v[j].z;
        p[3 * ST_STRIDE] = v[j].w;
    }
    __syncthreads();

    // ---- q_n = ||s_n||^2 (one n per thread), stored at SW(n) ----
    {
        const int pn = SW(tid);
        float q = 0.0f;
#pragma unroll
        for (int k0 = 0; k0 < D; k0 += 8) {
            const int hk = (k0 >> 3) << 2;
            const float* col = &st[k0 * ST_STRIDE + (pn ^ hk)];
#pragma unroll
            for (int kk = 0; kk < 8; kk++) {
                float val = col[kk * ST_STRIDE];
                q = fmaf(val, val, q);
            }
        }
        qn_s[pn] = q;
    }
    __syncthreads();

    // ---- dot GEMM (f32x2, no DUP2): thread = 4b x 8n, warp = 4b x 256n ----
    const int w    = tid >> 5;
    const int lane = tid & 31;
    const int b0   = 4 * w;
    const int pnA  = SW(8 * lane);

    float lg[4][8];
    {
        unsigned long long dot2[4][4];
#pragma unroll
        for (int a = 0; a < 4; a++)
#pragma unroll
            for (int jp = 0; jp < 4; jp++) dot2[a][jp] = 0ull;

#pragma unroll 1
        for (int k0 = 0; k0 < D; k0 += 8) {
            const int hk = (k0 >> 3) << 2;
            const int pA = pnA ^ hk;
#pragma unroll
            for (int kk = 0; kk < 8; kk++) {
                const int k = k0 + kk;
                // duplicated x pairs: (xb0,xb0),(xb1,xb1),(xb2,xb2),(xb3,xb3)
                const ulonglong2 x01 = *(const ulonglong2*)&xs2[k * XS2_STRIDE + 2 * b0];
                const ulonglong2 x23 = *(const ulonglong2*)&xs2[k * XS2_STRIDE + 2 * b0 + 4];
                const ulonglong2 s01 = *(const ulonglong2*)&st[k * ST_STRIDE + pA];
                const ulonglong2 s23 = *(const ulonglong2*)&st[k * ST_STRIDE + (pA ^ 4)];
                FMA2(dot2[0][0], x01.x, s01.x); FMA2(dot2[0][1], x01.x, s01.y);
                FMA2(dot2[0][2], x01.x, s23.x); FMA2(dot2[0][3], x01.x, s23.y);
                FMA2(dot2[1][0], x01.y, s01.x); FMA2(dot2[1][1], x01.y, s01.y);
                FMA2(dot2[1][2], x01.y, s23.x); FMA2(dot2[1][3], x01.y, s23.y);
                FMA2(dot2[2][0], x23.x, s01.x); FMA2(dot2[2][1], x23.x, s01.y);
                FMA2(dot2[2][2], x23.x, s23.x); FMA2(dot2[2][3], x23.x, s23.y);
                FMA2(dot2[3][0], x23.y, s01.x); FMA2(dot2[3][1], x23.y, s01.y);
                FMA2(dot2[3][2], x23.y, s23.x); FMA2(dot2[3][3], x23.y, s23.y);
            }
        }

        const float4 q0 = *(const float4*)&qn_s[pnA];
        const float4 q1 = *(const float4*)&qn_s[pnA ^ 4];
        const float qv[8] = {q0.x, q0.y, q0.z, q0.w, q1.x, q1.y, q1.z, q1.w};
#pragma unroll
        for (int a = 0; a < 4; a++) {
            const float c = cb_s[b0 + a];
#pragma unroll
            for (int jp = 0; jp < 4; jp++) {
                lg[a][2 * jp    ] = c * (2.0f * lo32(dot2[a][jp]) - qv[2 * jp]);
                lg[a][2 * jp + 1] = c * (2.0f * hi32(dot2[a][jp]) - qv[2 * jp + 1]);
            }
        }
    }
    __syncthreads();   // xs2 (aliasing G) dead everywhere before weights land

    // ---- softmax in registers; weights to G; m/l direct to global ----
#pragma unroll
    for (int a = 0; a < 4; a++) {
        float m = lg[a][0];
#pragma unroll
        for (int i = 1; i < 8; i++) m = fmaxf(m, lg[a][i]);
#pragma unroll
        for (int s = 16; s; s >>= 1) m = fmaxf(m, __shfl_xor_sync(0xffffffffu, m, s));
        float l = 0.0f;
#pragma unroll
        for (int i = 0; i < 8; i++) {
            float p = __expf(lg[a][i] - m);
            lg[a][i] = p;
            l += p;
        }
        *(float4*)&G[(b0 + a) * G_STRIDE + pnA] =
            make_float4(lg[a][0], lg[a][1], lg[a][2], lg[a][3]);
        *(float4*)&G[(b0 + a) * G_STRIDE + (pnA ^ 4)] =
            make_float4(lg[a][4], lg[a][5], lg[a][6], lg[a][7]);
#pragma unroll
        for (int s = 16; s; s >>= 1) l += __shfl_xor_sync(0xffffffffu, l, s);
        if (lane == 0) {
            g_mT[b0 + a][blockIdx.x] = m;
            g_lT[b0 + a][blockIdx.x] = l;
        }
    }
    __syncthreads();

    // ---- acc GEMM (f32x2): thread = 4b x 8d, n split 4-way ----
    const int qg   = tid >> 6;
    const int cell = tid & 63;
    const int dg   = cell & 7;
    const int bg2  = cell >> 3;
    const int b0a  = 4 * bg2;
    const int d0   = 8 * dg;
    const int hd   = dg << 2;

    unsigned long long acc2[4][8];
#pragma unroll
    for (int a = 0; a < 4; a++)
#pragma unroll
        for (int r = 0; r < 8; r++) acc2[a][r] = 0ull;

    {
        const int nbase = 64 * qg;
#pragma unroll 2
        for (int n4 = 0; n4 < 64; n4 += 4) {
            const int pg = SW(nbase + n4);
            const int ps = pg ^ hd;
            const ulonglong2 p0 = *(const ulonglong2*)&G[(b0a + 0) * G_STRIDE + pg];
            const ulonglong2 p1 = *(const ulonglong2*)&G[(b0a + 1) * G_STRIDE + pg];
            const ulonglong2 p2 = *(const ulonglong2*)&G[(b0a + 2) * G_STRIDE + pg];
            const ulonglong2 p3 = *(const ulonglong2*)&G[(b0a + 3) * G_STRIDE + pg];
#pragma unroll
            for (int r = 0; r < 8; r++) {
                const ulonglong2 sv = *(const ulonglong2*)&st[(d0 + r) * ST_STRIDE + ps];
                FMA2(acc2[0][r], p0.x, sv.x); FMA2(acc2[0][r], p0.y, sv.y);
                FMA2(acc2[1][r], p1.x, sv.x); FMA2(acc2[1][r], p1.y, sv.y);
                FMA2(acc2[2][r], p2.x, sv.x); FMA2(acc2[2][r], p2.y, sv.y);
                FMA2(acc2[3][r], p3.x, sv.x); FMA2(acc2[3][r], p3.y, sv.y);
            }
        }
    }

    float acc[4][8];
#pragma unroll
    for (int a = 0; a < 4; a++)
#pragma unroll
        for (int r = 0; r < 8; r++)
            acc[a][r] = lo32(acc2[a][r]) + hi32(acc2[a][r]);

    __syncthreads();            // done reading G/st; reuse G as combine buffer

    float* buf = G;             // 4*64*32 = 8192 floats = exactly G
    {
        float* bp = &buf[(qg * 64 + cell) * 32];
#pragma unroll
        for (int a = 0; a < 4; a++) {
            *(float4*)&bp[a * 8 + 0] = make_float4(acc[a][0], acc[a][1], acc[a][2], acc[a][3]);
            *(float4*)&bp[a * 8 + 4] = make_float4(acc[a][4], acc[a][5], acc[a][6], acc[a][7]);
        }
    }
    __syncthreads();
    {
        const int a2 = tid >> 6;
        const int c2 = tid & 63;
        float4 sA = make_float4(0.f, 0.f, 0.f, 0.f);
        float4 sB = make_float4(0.f, 0.f, 0.f, 0.f);
#pragma unroll
        for (int q2 = 0; q2 < 4; q2++) {
            const float* bp = &buf[(q2 * 64 + c2) * 32 + a2 * 8];
            const float4 uA = *(const float4*)&bp[0];
            const float4 uB = *(const float4*)&bp[4];
            sA.x += uA.x; sA.y += uA.y; sA.z += uA.z; sA.w += uA.w;
            sB.x += uB.x; sB.y += uB.y; sB.z += uB.z; sB.w += uB.w;
        }
        const int bglob = 4 * (c2 >> 3) + a2;
        const int dbase = 8 * (c2 & 7);
        *(float4*)&g_acc[blockIdx.x][bglob][dbase + 0] = sA;
        *(float4*)&g_acc[blockIdx.x][bglob][dbase + 4] = sB;
    }
}

// Distributed reduce: CTA owns (b = blk&31, d-octet = blk>>5).
__global__ __launch_bounds__(256)
void score_reduce_kernel(const float* __restrict__ t,
                         const float* __restrict__ x,
                         float* __restrict__ out) {
    const int b   = blockIdx.x & 31;
    const int d0r = (blockIdx.x >> 5) * 8;
    const int tid = threadIdx.x;
    __shared__ float red[416];

    const float mi = g_mT[b][tid];
    red[tid] = mi;
    __syncthreads();
    if (tid < 32) {
        float m = red[tid];
#pragma unroll
        for (int k = 1; k < 8; k++) m = fmaxf(m, red[tid + 32 * k]);
#pragma unroll
        for (int s = 16; s; s >>= 1) m = fmaxf(m, __shfl_xor_sync(0xffffffffu, m, s));
        if (tid == 0) red[300] = m;
    }
    __syncthreads();
    const float M = red[300];

    const float ei = __expf(mi - M);
    float vals[9];
    vals[0] = ei * g_lT[b][tid];
    {
        const float4 aA = *(const float4*)&g_acc[tid][b][d0r];
        const float4 aB = *(const float4*)&g_acc[tid][b][d0r + 4];
        vals[1] = ei * aA.x; vals[2] = ei * aA.y; vals[3] = ei * aA.z; vals[4] = ei * aA.w;
        vals[5] = ei * aB.x; vals[6] = ei * aB.y; vals[7] = ei * aB.z; vals[8] = ei * aB.w;
    }
#pragma unroll
    for (int s = 16; s; s >>= 1)
#pragma unroll
        for (int j = 0; j < 9; j++)
            vals[j] += __shfl_xor_sync(0xffffffffu, vals[j], s);
    const int w2 = tid >> 5;
    if ((tid & 31) == 0) {
#pragma unroll
        for (int j = 0; j < 9; j++) red[320 + w2 * 12 + j] = vals[j];
    }
    __syncthreads();
    if (tid < 8) {
        float L = 0.0f, A = 0.0f;
#pragma unroll
        for (int w3 = 0; w3 < 8; w3++) {
            L += red[320 + w3 * 12 + 0];
            A += red[320 + w3 * 12 + 1 + tid];
        }
        const float sig = 0.01f * expf(t[b] * 9.210340371976184f);
        out[b * D + d0r + tid] = (1.0f / sig) * (A / L - x[b * D + d0r + tid]);
    }
}

extern "C" void kernel_launch(void* const* d_in, const int* in_sizes, int n_in,
                              void* d_out, int out_size) {
    const float* t = nullptr;
    const float* x = nullptr;
    const float* s = nullptr;
    for (int i = 0; i < n_in; i++) {
        if      (in_sizes[i] == B)      t = (const float*)d_in[i];
        else if (in_sizes[i] == B * D)  x = (const float*)d_in[i];
        else if (in_sizes[i] == NS * D) s = (const float*)d_in[i];
    }
    cudaFuncSetAttribute(score_partial_kernel,
                         cudaFuncAttributeMaxDynamicSharedMemorySize, SMEM_BYTES);
    score_partial_kernel<<<GRID_MAIN, THREADS, SMEM_BYTES>>>(t, x, s);
    score_reduce_kernel<<<GRID_MAIN, 256>>>(t, x, (float*)d_out);
}

// round 13
// speedup vs baseline: 1.0500x; 1.0459x over previous
// SampleScoreModel: softmax-weighted Gaussian-kernel score (flash-attention style).
// Round 13: K1 = exact round-4 kernel (best measured main phase, 23.6us),
// m/l writes transposed. K2 = grid-256 distributed reduce launched with
// PROGRAMMATIC DEPENDENT LAUNCH: K2's launch+prologue overlaps K1; it blocks in
// cudaGridDependencySynchronize() until K1's writes are visible. Hides the
// ~5-6us serialized short-kernel floor of the reduce tail.
#include <cuda_runtime.h>
#include <math.h>
#include <float.h>

#define B 32
#define D 64
#define NS 65536
#define TILE 256
#define GRID_MAIN (NS / TILE)   // 256
#define THREADS 256

#define ST_STRIDE 256
#define G_STRIDE 256
#define XS_STRIDE 36

#define SW(n) ((n) ^ ((((n) >> 3) & 7) << 2))

// smem layout (floats)
#define OFF_ST 0                         // 64*256 = 16384
#define OFF_G  16384                     // 32*256 = 8192
#define OFF_XS 24576                     // 64*36  = 2304
#define OFF_Q  26880                     // 256
#define OFF_CB 27136                     // 32
#define OFF_M  27168                     // 32
#define OFF_L  27200                     // 32
#define SMEM_FLOATS 27232
#define SMEM_BYTES (SMEM_FLOATS * 4)     // 108,928 B -> 2 CTAs/SM

#define FMA2(acc, a, b) \
    asm("fma.rn.f32x2 %0, %1, %2, %0;" : "+l"(acc) : "l"(a), "l"(b))
#define DUP2(d, f) \
    asm("mov.b64 %0, {%1, %1};" : "=l"(d) : "r"(__float_as_uint(f)))

__device__ __forceinline__ float lo32(unsigned long long u) {
    return __uint_as_float((unsigned)u);
}
__device__ __forceinline__ float hi32(unsigned long long u) {
    return __uint_as_float((unsigned)(u >> 32));
}

__device__ float g_acc[GRID_MAIN][B][D];
__device__ float g_mT[B][GRID_MAIN];    // transposed: coalesced reduce reads
__device__ float g_lT[B][GRID_MAIN];

__global__ __launch_bounds__(THREADS, 2)
void score_partial_kernel(const float* __restrict__ t,
                          const float* __restrict__ x,
                          const float* __restrict__ samples) {
    extern __shared__ float sm[];
    float* st   = sm + OFF_ST;
    float* G    = sm + OFF_G;
    float* xs   = sm + OFF_XS;
    float* qn_s = sm + OFF_Q;
    float* cb_s = sm + OFF_CB;
    float* m_s  = sm + OFF_M;
    float* l_s  = sm + OFF_L;

    const int tid = threadIdx.x;

    // ---- setup: x transpose + per-b constants ----
#pragma unroll
    for (int i = tid; i < B * D; i += THREADS) {
        int b = i >> 6, k = i & 63;
        xs[k * XS_STRIDE + b] = x[i];
    }
    if (tid < B) {
        float sig = 0.01f * expf(t[tid] * 9.210340371976184f);
        cb_s[tid] = 0.5f / (sig * sig);
    }

    // ---- coalesced global load: flat float4 index = tid + 256*j ----
    const int nn2 = tid >> 4;
    const int d4  = tid & 15;
    const float4* sp = (const float4*)samples;
    const size_t base = (size_t)blockIdx.x * (TILE * (D / 4));
    float4 v[16];
#pragma unroll
    for (int j = 0; j < 16; j++) v[j] = sp[base + tid + 256 * j];

    // ---- transpose-store into st with d-dependent swizzle ----
    const int h4st = (d4 >> 1) << 2;
#pragma unroll
    for (int j = 0; j < 16; j++) {
        int n = 16 * j + nn2;
        int pc = SW(n) ^ h4st;
        float* p = &st[(4 * d4) * ST_STRIDE + pc];
        p[0 * ST_STRIDE] = v[j].x;
        p[1 * ST_STRIDE] = v[j].y;
        p[2 * ST_STRIDE] = v[j].z;
        p[3 * ST_STRIDE] = v[j].w;
    }
    __syncthreads();

    // ---- q_n = ||s_n||^2, stored at SW(n) ----
    {
        const int pn = SW(tid);
        float q = 0.0f;
#pragma unroll
        for (int k0 = 0; k0 < D; k0 += 8) {
            const int hk = (k0 >> 3) << 2;
            const float* col = &st[k0 * ST_STRIDE + (pn ^ hk)];
#pragma unroll
            for (int kk = 0; kk < 8; kk++) {
                float val = col[kk * ST_STRIDE];
                q = fmaf(val, val, q);
            }
        }
        qn_s[pn] = q;
    }
    __syncthreads();

    // ---- dot GEMM (f32x2, n-paired): 4b x 8n/thread; fused register softmax ----
    {
        const int w    = tid >> 5;
        const int lane = tid & 31;
        const int b0   = 4 * w;
        const int pnA  = SW(8 * lane);

        unsigned long long dot2[4][4];
#pragma unroll
        for (int a = 0; a < 4; a++)
#pragma unroll
            for (int jp = 0; jp < 4; jp++) dot2[a][jp] = 0ull;

#pragma unroll 1
        for (int k0 = 0; k0 < D; k0 += 8) {
            const int hk = (k0 >> 3) << 2;
            const int pA = pnA ^ hk;
#pragma unroll
            for (int kk = 0; kk < 8; kk++) {
                const int k = k0 + kk;
                const float4 xv = *(const float4*)&xs[k * XS_STRIDE + b0];
                unsigned long long xd0, xd1, xd2, xd3;
                DUP2(xd0, xv.x); DUP2(xd1, xv.y); DUP2(xd2, xv.z); DUP2(xd3, xv.w);
                const ulonglong2 s01 = *(const ulonglong2*)&st[k * ST_STRIDE + pA];
                const ulonglong2 s23 = *(const ulonglong2*)&st[k * ST_STRIDE + (pA ^ 4)];
                FMA2(dot2[0][0], xd0, s01.x); FMA2(dot2[0][1], xd0, s01.y);
                FMA2(dot2[0][2], xd0, s23.x); FMA2(dot2[0][3], xd0, s23.y);
                FMA2(dot2[1][0], xd1, s01.x); FMA2(dot2[1][1], xd1, s01.y);
                FMA2(dot2[1][2], xd1, s23.x); FMA2(dot2[1][3], xd1, s23.y);
                FMA2(dot2[2][0], xd2, s01.x); FMA2(dot2[2][1], xd2, s01.y);
                FMA2(dot2[2][2], xd2, s23.x); FMA2(dot2[2][3], xd2, s23.y);
                FMA2(dot2[3][0], xd3, s01.x); FMA2(dot2[3][1], xd3, s01.y);
                FMA2(dot2[3][2], xd3, s23.x); FMA2(dot2[3][3], xd3, s23.y);
            }
        }

        const float4 q0 = *(const float4*)&qn_s[pnA];
        const float4 q1 = *(const float4*)&qn_s[pnA ^ 4];
        const float qv[8] = {q0.x, q0.y, q0.z, q0.w, q1.x, q1.y, q1.z, q1.w};

#pragma unroll
        for (int a = 0; a < 4; a++) {
            const float c = cb_s[b0 + a];
            float gv[8];
#pragma unroll
            for (int jp = 0; jp < 4; jp++) {
                gv[2 * jp    ] = c * (2.0f * lo32(dot2[a][jp]) - qv[2 * jp]);
                gv[2 * jp + 1] = c * (2.0f * hi32(dot2[a][jp]) - qv[2 * jp + 1]);
            }
            float m = gv[0];
#pragma unroll
            for (int i = 1; i < 8; i++) m = fmaxf(m, gv[i]);
#pragma unroll
            for (int s = 16; s; s >>= 1) m = fmaxf(m, __shfl_xor_sync(0xffffffffu, m, s));
            float l = 0.0f;
#pragma unroll
            for (int i = 0; i < 8; i++) {
                float p = __expf(gv[i] - m);
                gv[i] = p;
                l += p;
            }
            *(float4*)&G[(b0 + a) * G_STRIDE + pnA] =
                make_float4(gv[0], gv[1], gv[2], gv[3]);
            *(float4*)&G[(b0 + a) * G_STRIDE + (pnA ^ 4)] =
                make_float4(gv[4], gv[5], gv[6], gv[7]);
#pragma unroll
            for (int s = 16; s; s >>= 1) l += __shfl_xor_sync(0xffffffffu, l, s);
            if (lane == 0) { m_s[b0 + a] = m; l_s[b0 + a] = l; }
        }
    }
    __syncthreads();

    // ---- acc GEMM (f32x2): 4b x 8d/thread, n split 4-way ----
    const int qg   = tid >> 6;
    const int cell = tid & 63;
    const int dg   = cell & 7;
    const int bg2  = cell >> 3;
    const int b0a  = 4 * bg2;
    const int d0   = 8 * dg;
    const int hd   = dg << 2;

    unsigned long long acc2[4][8];
#pragma unroll
    for (int a = 0; a < 4; a++)
#pragma unroll
        for (int r = 0; r < 8; r++) acc2[a][r] = 0ull;

    {
        const int nbase = 64 * qg;
#pragma unroll 2
        for (int n4 = 0; n4 < 64; n4 += 4) {
            const int pg = SW(nbase + n4);
            const int ps = pg ^ hd;
            const ulonglong2 p0 = *(const ulonglong2*)&G[(b0a + 0) * G_STRIDE + pg];
            const ulonglong2 p1 = *(const ulonglong2*)&G[(b0a + 1) * G_STRIDE + pg];
            const ulonglong2 p2 = *(const ulonglong2*)&G[(b0a + 2) * G_STRIDE + pg];
            const ulonglong2 p3 = *(const ulonglong2*)&G[(b0a + 3) * G_STRIDE + pg];
#pragma unroll
            for (int r = 0; r < 8; r++) {
                const ulonglong2 sv = *(const ulonglong2*)&st[(d0 + r) * ST_STRIDE + ps];
                FMA2(acc2[0][r], p0.x, sv.x); FMA2(acc2[0][r], p0.y, sv.y);
                FMA2(acc2[1][r], p1.x, sv.x); FMA2(acc2[1][r], p1.y, sv.y);
                FMA2(acc2[2][r], p2.x, sv.x); FMA2(acc2[2][r], p2.y, sv.y);
                FMA2(acc2[3][r], p3.x, sv.x); FMA2(acc2[3][r], p3.y, sv.y);
            }
        }
    }

    float acc[4][8];
#pragma unroll
    for (int a = 0; a < 4; a++)
#pragma unroll
        for (int r = 0; r < 8; r++)
            acc[a][r] = lo32(acc2[a][r]) + hi32(acc2[a][r]);

    __syncthreads();            // done reading G; reuse as combine buffer

    float* buf = G;
    {
        float* bp = &buf[(qg * 64 + cell) * 32];
#pragma unroll
        for (int a = 0; a < 4; a++) {
            *(float4*)&bp[a * 8 + 0] = make_float4(acc[a][0], acc[a][1], acc[a][2], acc[a][3]);
            *(float4*)&bp[a * 8 + 4] = make_float4(acc[a][4], acc[a][5], acc[a][6], acc[a][7]);
        }
    }
    __syncthreads();
    {
        const int a2 = tid >> 6;
        const int c2 = tid & 63;
        float4 sA = make_float4(0.f, 0.f, 0.f, 0.f);
        float4 sB = make_float4(0.f, 0.f, 0.f, 0.f);
#pragma unroll
        for (int q2 = 0; q2 < 4; q2++) {
            const float* bp = &buf[(q2 * 64 + c2) * 32 + a2 * 8];
            const float4 uA = *(const float4*)&bp[0];
            const float4 uB = *(const float4*)&bp[4];
            sA.x += uA.x; sA.y += uA.y; sA.z += uA.z; sA.w += uA.w;
            sB.x += uB.x; sB.y += uB.y; sB.z += uB.z; sB.w += uB.w;
        }
        const int bglob = 4 * (c2 >> 3) + a2;
        const int dbase = 8 * (c2 & 7);
        *(float4*)&g_acc[blockIdx.x][bglob][dbase + 0] = sA;
        *(float4*)&g_acc[blockIdx.x][bglob][dbase + 4] = sB;
    }
    if (tid < B) {
        g_mT[tid][blockIdx.x] = m_s[tid];
        g_lT[tid][blockIdx.x] = l_s[tid];
    }
}

// Distributed reduce with PDL: launch+prologue overlap K1; block until K1's
// grid completes (implicit completion trigger) before touching its outputs.
__global__ __launch_bounds__(256)
void score_reduce_kernel(const float* __restrict__ t,
                         const float* __restrict__ x,
                         float* __restrict__ out) {
    const int b   = blockIdx.x & 31;
    const int d0r = (blockIdx.x >> 5) * 8;
    const int tid = threadIdx.x;
    __shared__ float red[416];

    cudaGridDependencySynchronize();   // wait for score_partial_kernel

    const float mi = g_mT[b][tid];
    red[tid] = mi;
    __syncthreads();
    if (tid < 32) {
        float m = red[tid];
#pragma unroll
        for (int k = 1; k < 8; k++) m = fmaxf(m, red[tid + 32 * k]);
#pragma unroll
        for (int s = 16; s; s >>= 1) m = fmaxf(m, __shfl_xor_sync(0xffffffffu, m, s));
        if (tid == 0) red[300] = m;
    }
    __syncthreads();
    const float M = red[300];

    const float ei = __expf(mi - M);
    float vals[9];
    vals[0] = ei * g_lT[b][tid];
    {
        const float4 aA = *(const float4*)&g_acc[tid][b][d0r];
        const float4 aB = *(const float4*)&g_acc[tid][b][d0r + 4];
        vals[1] = ei * aA.x; vals[2] = ei * aA.y; vals[3] = ei * aA.z; vals[4] = ei * aA.w;
        vals[5] = ei * aB.x; vals[6] = ei * aB.y; vals[7] = ei * aB.z; vals[8] = ei * aB.w;
    }
#pragma unroll
    for (int s = 16; s; s >>= 1)
#pragma unroll
        for (int j = 0; j < 9; j++)
            vals[j] += __shfl_xor_sync(0xffffffffu, vals[j], s);
    const int w2 = tid >> 5;
    if ((tid & 31) == 0) {
#pragma unroll
        for (int j = 0; j < 9; j++) red[320 + w2 * 12 + j] = vals[j];
    }
    __syncthreads();
    if (tid < 8) {
        float L = 0.0f, A = 0.0f;
#pragma unroll
        for (int w3 = 0; w3 < 8; w3++) {
            L += red[320 + w3 * 12 + 0];
            A += red[320 + w3 * 12 + 1 + tid];
        }
        const float sig = 0.01f * expf(t[b] * 9.210340371976184f);
        out[b * D + d0r + tid] = (1.0f / sig) * (A / L - x[b * D + d0r + tid]);
    }
}

extern "C" void kernel_launch(void* const* d_in, const int* in_sizes, int n_in,
                              void* d_out, int out_size) {
    const float* t = nullptr;
    const float* x = nullptr;
    const float* s = nullptr;
    for (int i = 0; i < n_in; i++) {
        if      (in_sizes[i] == B)      t = (const float*)d_in[i];
        else if (in_sizes[i] == B * D)  x = (const float*)d_in[i];
        else if (in_sizes[i] == NS * D) s = (const float*)d_in[i];
    }
    cudaFuncSetAttribute(score_partial_kernel,
                         cudaFuncAttributeMaxDynamicSharedMemorySize, SMEM_BYTES);
    score_partial_kernel<<<GRID_MAIN, THREADS, SMEM_BYTES>>>(t, x, s);

    // PDL launch of the reduce: overlaps its launch/prologue with K1.
    cudaLaunchAttribute attrs[1];
    attrs[0].id = cudaLaunchAttributeProgrammaticStreamSerialization;
    attrs[0].val.programmaticStreamSerializationAllowed = 1;
    cudaLaunchConfig_t cfg = {};
    cfg.gridDim = dim3(GRID_MAIN, 1, 1);
    cfg.blockDim = dim3(256, 1, 1);
    cfg.dynamicSmemBytes = 0;
    cfg.stream = 0;
    cfg.attrs = attrs;
    cfg.numAttrs = 1;
    cudaLaunchKernelEx(&cfg, score_reduce_kernel, t, x, (float*)d_out);
}

// round 14
// speedup vs baseline: 1.0708x; 1.0198x over previous
// SampleScoreModel: softmax-weighted Gaussian-kernel score (flash-attention style).
// Round 14: K1 = r13 with the q-pass FUSED into the dot loop (removes 512 LDS
// wavefronts/CTA + one barrier + qn_s round-trip; q accumulated as packed FMA2
// squares on the already-loaded st operands). K2 = r13 reduce with g_acc/g_l
// loads hoisted before the max phase. PDL kept (harmless).
#include <cuda_runtime.h>
#include <math.h>
#include <float.h>

#define B 32
#define D 64
#define NS 65536
#define TILE 256
#define GRID_MAIN (NS / TILE)   // 256
#define THREADS 256

#define ST_STRIDE 256
#define G_STRIDE 256
#define XS_STRIDE 36

#define SW(n) ((n) ^ ((((n) >> 3) & 7) << 2))

// smem layout (floats)
#define OFF_ST 0                         // 64*256 = 16384
#define OFF_G  16384                     // 32*256 = 8192
#define OFF_XS 24576                     // 64*36  = 2304
#define OFF_CB 26880                     // 32
#define OFF_M  26912                     // 32
#define OFF_L  26944                     // 32
#define SMEM_FLOATS 26976
#define SMEM_BYTES (SMEM_FLOATS * 4)     // 107,904 B -> 2 CTAs/SM

#define FMA2(acc, a, b) \
    asm("fma.rn.f32x2 %0, %1, %2, %0;" : "+l"(acc) : "l"(a), "l"(b))
#define DUP2(d, f) \
    asm("mov.b64 %0, {%1, %1};" : "=l"(d) : "r"(__float_as_uint(f)))

__device__ __forceinline__ float lo32(unsigned long long u) {
    return __uint_as_float((unsigned)u);
}
__device__ __forceinline__ float hi32(unsigned long long u) {
    return __uint_as_float((unsigned)(u >> 32));
}

__device__ float g_acc[GRID_MAIN][B][D];
__device__ float g_mT[B][GRID_MAIN];    // transposed: coalesced reduce reads
__device__ float g_lT[B][GRID_MAIN];

__global__ __launch_bounds__(THREADS, 2)
void score_partial_kernel(const float* __restrict__ t,
                          const float* __restrict__ x,
                          const float* __restrict__ samples) {
    extern __shared__ float sm[];
    float* st   = sm + OFF_ST;
    float* G    = sm + OFF_G;
    float* xs   = sm + OFF_XS;
    float* cb_s = sm + OFF_CB;
    float* m_s  = sm + OFF_M;
    float* l_s  = sm + OFF_L;

    const int tid = threadIdx.x;

    // ---- coalesced global load issued FIRST (16-deep MLP in flight) ----
    const int nn2 = tid >> 4;
    const int d4  = tid & 15;
    const float4* sp = (const float4*)samples;
    const size_t base = (size_t)blockIdx.x * (TILE * (D / 4));
    float4 v[16];
#pragma unroll
    for (int j = 0; j < 16; j++) v[j] = sp[base + tid + 256 * j];

    // ---- setup: x transpose + per-b constants (overlaps inflight loads) ----
#pragma unroll
    for (int i = tid; i < B * D; i += THREADS) {
        int b = i >> 6, k = i & 63;
        xs[k * XS_STRIDE + b] = x[i];
    }
    if (tid < B) {
        float sig = 0.01f * expf(t[tid] * 9.210340371976184f);
        cb_s[tid] = 0.5f / (sig * sig);
    }

    // ---- transpose-store into st with d-dependent swizzle ----
    const int h4st = (d4 >> 1) << 2;
#pragma unroll
    for (int j = 0; j < 16; j++) {
        int n = 16 * j + nn2;
        int pc = SW(n) ^ h4st;
        float* p = &st[(4 * d4) * ST_STRIDE + pc];
        p[0 * ST_STRIDE] = v[j].x;
        p[1 * ST_STRIDE] = v[j].y;
        p[2 * ST_STRIDE] = v[j].z;
        p[3 * ST_STRIDE] = v[j].w;
    }
    __syncthreads();

    // ---- dot GEMM with FUSED q: 4b x 8n/thread; register softmax ----
    {
        const int w    = tid >> 5;
        const int lane = tid & 31;
        const int b0   = 4 * w;
        const int pnA  = SW(8 * lane);

        unsigned long long dot2[4][4];
        unsigned long long q2[4];       // packed sum-of-squares for the 8 n's
#pragma unroll
        for (int a = 0; a < 4; a++) {
#pragma unroll
            for (int jp = 0; jp < 4; jp++) dot2[a][jp] = 0ull;
            q2[a] = 0ull;
        }

#pragma unroll 1
        for (int k0 = 0; k0 < D; k0 += 8) {
            const int hk = (k0 >> 3) << 2;
            const int pA = pnA ^ hk;
#pragma unroll
            for (int kk = 0; kk < 8; kk++) {
                const int k = k0 + kk;
                const float4 xv = *(const float4*)&xs[k * XS_STRIDE + b0];
                unsigned long long xd0, xd1, xd2, xd3;
                DUP2(xd0, xv.x); DUP2(xd1, xv.y); DUP2(xd2, xv.z); DUP2(xd3, xv.w);
                const ulonglong2 s01 = *(const ulonglong2*)&st[k * ST_STRIDE + pA];
                const ulonglong2 s23 = *(const ulonglong2*)&st[k * ST_STRIDE + (pA ^ 4)];
                FMA2(dot2[0][0], xd0, s01.x); FMA2(dot2[0][1], xd0, s01.y);
                FMA2(dot2[0][2], xd0, s23.x); FMA2(dot2[0][3], xd0, s23.y);
                FMA2(dot2[1][0], xd1, s01.x); FMA2(dot2[1][1], xd1, s01.y);
                FMA2(dot2[1][2], xd1, s23.x); FMA2(dot2[1][3], xd1, s23.y);
                FMA2(dot2[2][0], xd2, s01.x); FMA2(dot2[2][1], xd2, s01.y);
                FMA2(dot2[2][2], xd2, s23.x); FMA2(dot2[2][3], xd2, s23.y);
                FMA2(dot2[3][0], xd3, s01.x); FMA2(dot2[3][1], xd3, s01.y);
                FMA2(dot2[3][2], xd3, s23.x); FMA2(dot2[3][3], xd3, s23.y);
                FMA2(q2[0], s01.x, s01.x);   FMA2(q2[1], s01.y, s01.y);
                FMA2(q2[2], s23.x, s23.x);   FMA2(q2[3], s23.y, s23.y);
            }
        }

        const float qv[8] = {lo32(q2[0]), hi32(q2[0]), lo32(q2[1]), hi32(q2[1]),
                             lo32(q2[2]), hi32(q2[2]), lo32(q2[3]), hi32(q2[3])};

#pragma unroll
        for (int a = 0; a < 4; a++) {
            const float c = cb_s[b0 + a];
            float gv[8];
#pragma unroll
            for (int jp = 0; jp < 4; jp++) {
                gv[2 * jp    ] = c * (2.0f * lo32(dot2[a][jp]) - qv[2 * jp]);
                gv[2 * jp + 1] = c * (2.0f * hi32(dot2[a][jp]) - qv[2 * jp + 1]);
            }
            float m = gv[0];
#pragma unroll
            for (int i = 1; i < 8; i++) m = fmaxf(m, gv[i]);
#pragma unroll
            for (int s = 16; s; s >>= 1) m = fmaxf(m, __shfl_xor_sync(0xffffffffu, m, s));
            float l = 0.0f;
#pragma unroll
            for (int i = 0; i < 8; i++) {
                float p = __expf(gv[i] - m);
                gv[i] = p;
                l += p;
            }
            *(float4*)&G[(b0 + a) * G_STRIDE + pnA] =
                make_float4(gv[0], gv[1], gv[2], gv[3]);
            *(float4*)&G[(b0 + a) * G_STRIDE + (pnA ^ 4)] =
                make_float4(gv[4], gv[5], gv[6], gv[7]);
#pragma unroll
            for (int s = 16; s; s >>= 1) l += __shfl_xor_sync(0xffffffffu, l, s);
            if (lane == 0) { m_s[b0 + a] = m; l_s[b0 + a] = l; }
        }
    }
    __syncthreads();

    // ---- acc GEMM (f32x2): 4b x 8d/thread, n split 4-way ----
    const int qg   = tid >> 6;
    const int cell = tid & 63;
    const int dg   = cell & 7;
    const int bg2  = cell >> 3;
    const int b0a  = 4 * bg2;
    const int d0   = 8 * dg;
    const int hd   = dg << 2;

    unsigned long long acc2[4][8];
#pragma unroll
    for (int a = 0; a < 4; a++)
#pragma unroll
        for (int r = 0; r < 8; r++) acc2[a][r] = 0ull;

    {
        const int nbase = 64 * qg;
#pragma unroll 2
        for (int n4 = 0; n4 < 64; n4 += 4) {
            const int pg = SW(nbase + n4);
            const int ps = pg ^ hd;
            const ulonglong2 p0 = *(const ulonglong2*)&G[(b0a + 0) * G_STRIDE + pg];
            const ulonglong2 p1 = *(const ulonglong2*)&G[(b0a + 1) * G_STRIDE + pg];
            const ulonglong2 p2 = *(const ulonglong2*)&G[(b0a + 2) * G_STRIDE + pg];
            const ulonglong2 p3 = *(const ulonglong2*)&G[(b0a + 3) * G_STRIDE + pg];
#pragma unroll
            for (int r = 0; r < 8; r++) {
                const ulonglong2 sv = *(const ulonglong2*)&st[(d0 + r) * ST_STRIDE + ps];
                FMA2(acc2[0][r], p0.x, sv.x); FMA2(acc2[0][r], p0.y, sv.y);
                FMA2(acc2[1][r], p1.x, sv.x); FMA2(acc2[1][r], p1.y, sv.y);
                FMA2(acc2[2][r], p2.x, sv.x); FMA2(acc2[2][r], p2.y, sv.y);
                FMA2(acc2[3][r], p3.x, sv.x); FMA2(acc2[3][r], p3.y, sv.y);
            }
        }
    }

    float acc[4][8];
#pragma unroll
    for (int a = 0; a < 4; a++)
#pragma unroll
        for (int r = 0; r < 8; r++)
            acc[a][r] = lo32(acc2[a][r]) + hi32(acc2[a][r]);

    __syncthreads();            // done reading G; reuse as combine buffer

    float* buf = G;
    {
        float* bp = &buf[(qg * 64 + cell) * 32];
#pragma unroll
        for (int a = 0; a < 4; a++) {
            *(float4*)&bp[a * 8 + 0] = make_float4(acc[a][0], acc[a][1], acc[a][2], acc[a][3]);
            *(float4*)&bp[a * 8 + 4] = make_float4(acc[a][4], acc[a][5], acc[a][6], acc[a][7]);
        }
    }
    __syncthreads();
    {
        const int a2 = tid >> 6;
        const int c2 = tid & 63;
        float4 sA = make_float4(0.f, 0.f, 0.f, 0.f);
        float4 sB = make_float4(0.f, 0.f, 0.f, 0.f);
#pragma unroll
        for (int q2i = 0; q2i < 4; q2i++) {
            const float* bp = &buf[(q2i * 64 + c2) * 32 + a2 * 8];
            const float4 uA = *(const float4*)&bp[0];
            const float4 uB = *(const float4*)&bp[4];
            sA.x += uA.x; sA.y += uA.y; sA.z += uA.z; sA.w += uA.w;
            sB.x += uB.x; sB.y += uB.y; sB.z += uB.z; sB.w += uB.w;
        }
        const int bglob = 4 * (c2 >> 3) + a2;
        const int dbase = 8 * (c2 & 7);
        *(float4*)&g_acc[blockIdx.x][bglob][dbase + 0] = sA;
        *(float4*)&g_acc[blockIdx.x][bglob][dbase + 4] = sB;
    }
    if (tid < B) {
        g_mT[tid][blockIdx.x] = m_s[tid];
        g_lT[tid][blockIdx.x] = l_s[tid];
    }
}

// Distributed reduce: CTA owns (b = blk&31, d-octet = blk>>5).
// g_acc / g_l loads hoisted BEFORE the max phase (independent of M).
__global__ __launch_bounds__(256)
void score_reduce_kernel(const float* __restrict__ t,
                         const float* __restrict__ x,
                         float* __restrict__ out) {
    const int b   = blockIdx.x & 31;
    const int d0r = (blockIdx.x >> 5) * 8;
    const int tid = threadIdx.x;
    __shared__ float red[416];

    cudaGridDependencySynchronize();   // wait for score_partial_kernel

    // issue ALL loads up front (m, l, acc) — max latency overlap
    const float mi = g_mT[b][tid];
    const float li = g_lT[b][tid];
    const float4 aA = *(const float4*)&g_acc[tid][b][d0r];
    const float4 aB = *(const float4*)&g_acc[tid][b][d0r + 4];

    red[tid] = mi;
    __syncthreads();
    if (tid < 32) {
        float m = red[tid];
#pragma unroll
        for (int k = 1; k < 8; k++) m = fmaxf(m, red[tid + 32 * k]);
#pragma unroll
        for (int s = 16; s; s >>= 1) m = fmaxf(m, __shfl_xor_sync(0xffffffffu, m, s));
        if (tid == 0) red[300] = m;
    }
    __syncthreads();
    const float M = red[300];

    const float ei = __expf(mi - M);
    float vals[9];
    vals[0] = ei * li;
    vals[1] = ei * aA.x; vals[2] = ei * aA.y; vals[3] = ei * aA.z; vals[4] = ei * aA.w;
    vals[5] = ei * aB.x; vals[6] = ei * aB.y; vals[7] = ei * aB.z; vals[8] = ei * aB.w;
#pragma unroll
    for (int s = 16; s; s >>= 1)
#pragma unroll
        for (int j = 0; j < 9; j++)
            vals[j] += __shfl_xor_sync(0xffffffffu, vals[j], s);
    const int w2 = tid >> 5;
    if ((tid & 31) == 0) {
#pragma unroll
        for (int j = 0; j < 9; j++) red[320 + w2 * 12 + j] = vals[j];
    }
    __syncthreads();
    if (tid < 8) {
        float L = 0.0f, A = 0.0f;
#pragma unroll
        for (int w3 = 0; w3 < 8; w3++) {
            L += red[320 + w3 * 12 + 0];
            A += red[320 + w3 * 12 + 1 + tid];
        }
        const float sig = 0.01f * expf(t[b] * 9.210340371976184f);
        out[b * D + d0r + tid] = (1.0f / sig) * (A / L - x[b * D + d0r + tid]);
    }
}

extern "C" void kernel_launch(void* const* d_in, const int* in_sizes, int n_in,
                              void* d_out, int out_size) {
    const float* t = nullptr;
    const float* x = nullptr;
    const float* s = nullptr;
    for (int i = 0; i < n_in; i++) {
        if      (in_sizes[i] == B)      t = (const float*)d_in[i];
        else if (in_sizes[i] == B * D)  x = (const float*)d_in[i];
        else if (in_sizes[i] == NS * D) s = (const float*)d_in[i];
    }
    cudaFuncSetAttribute(score_partial_kernel,
                         cudaFuncAttributeMaxDynamicSharedMemorySize, SMEM_BYTES);
    score_partial_kernel<<<GRID_MAIN, THREADS, SMEM_BYTES>>>(t, x, s);

    cudaLaunchAttribute attrs[1];
    attrs[0].id = cudaLaunchAttributeProgrammaticStreamSerialization;
    attrs[0].val.programmaticStreamSerializationAllowed = 1;
    cudaLaunchConfig_t cfg = {};
    cfg.gridDim = dim3(GRID_MAIN, 1, 1);
    cfg.blockDim = dim3(256, 1, 1);
    cfg.dynamicSmemBytes = 0;
    cfg.stream = 0;
    cfg.attrs = attrs;
    cfg.numAttrs = 1;
    cudaLaunchKernelEx(&cfg, score_reduce_kernel, t, x, (float*)d_out);
}